// round 7
// baseline (speedup 1.0000x reference)
#include <cuda_runtime.h>
#include <cuda_bf16.h>
#include <cstdint>

// ---------------- problem constants ----------------
#define NUM_SPARSE   26
#define NCHUNK       28           // user + item + 26 sparse, K=64 each
#define TILE_B       128
#define STAGES       4
#define SPARSE_VOCAB 100000
#define THREADS      640          // 16 consumer warps + 4 producer warps

// bf16 rows: 64 bf16 = 128B + 16B pad = 144B (4-bank rotation per row, conflict-free ldmatrix)
#define ROWE 72                   // bf16 elems per row incl pad
#define ROWB 144                  // bytes per row
#define A_TILE_BYTES (TILE_B * ROWB)     // 18432
#define W_TILE_BYTES (128 * ROWB)        // 18432

// smem offsets (from 256-aligned base)
#define OFF_A    0
#define OFF_W    (STAGES * A_TILE_BYTES)                  // 73728
#define OFF_IDS  (OFF_W + STAGES * W_TILE_BYTES)          // 147456
#define OFF_B1   (OFF_IDS + NCHUNK * TILE_B * 4)          // 161792
#define OFF_W2   (OFF_B1 + 512)                           // 162304
#define OFF_PART (OFF_W2 + 512)                           // 162816 (512 f32)
#define OFF_MBAR (OFF_PART + 2048)                        // 164864 (8 x 8B)
#define SMEM_USED (OFF_MBAR + 128)
#define SMEM_DYN  (SMEM_USED + 256)                       // ~165.2 KB

// W1 bf16 transposed scratch: [chunk][n=128][72 bf16]
__device__ __align__(256) __nv_bfloat16 g_Wtb[NCHUNK * 128 * ROWE];

// ---------------- helpers ----------------
__device__ __forceinline__ uint32_t smem_u32(const void* p) {
    uint32_t a;
    asm("{ .reg .u64 t; cvta.to.shared.u64 t, %1; cvt.u32.u64 %0, t; }" : "=r"(a) : "l"(p));
    return a;
}
__device__ __forceinline__ void mbar_init(uint32_t m, uint32_t cnt) {
    asm volatile("mbarrier.init.shared.b64 [%0], %1;" :: "r"(m), "r"(cnt) : "memory");
}
__device__ __forceinline__ void mbar_expect_tx(uint32_t m, uint32_t bytes) {
    asm volatile("mbarrier.arrive.expect_tx.shared.b64 _, [%0], %1;" :: "r"(m), "r"(bytes) : "memory");
}
__device__ __forceinline__ void mbar_arrive(uint32_t m) {
    asm volatile("mbarrier.arrive.release.cta.shared::cta.b64 _, [%0];" :: "r"(m) : "memory");
}
__device__ __forceinline__ void mbar_wait(uint32_t m, uint32_t parity) {
    asm volatile(
        "{\n\t.reg .pred P;\n\t"
        "W%=:\n\t"
        "mbarrier.try_wait.parity.acquire.cta.shared::cta.b64 P, [%0], %1, 0x989680;\n\t"
        "@!P bra W%=;\n\t}"
        :: "r"(m), "r"(parity) : "memory");
}
__device__ __forceinline__ void bulk_g2s(uint32_t dst, const void* src, uint32_t bytes,
                                         uint32_t mbar) {
    asm volatile(
        "cp.async.bulk.shared::cluster.global.mbarrier::complete_tx::bytes [%0], [%1], %2, [%3];"
        :: "r"(dst), "l"(src), "r"(bytes), "r"(mbar) : "memory");
}
__device__ __forceinline__ void sts64(uint32_t addr, uint32_t p0, uint32_t p1) {
    asm volatile("st.shared.v2.u32 [%0], {%1, %2};" :: "r"(addr), "r"(p0), "r"(p1) : "memory");
}
__device__ __forceinline__ void ldm4(uint32_t* r, uint32_t addr) {
    asm volatile("ldmatrix.sync.aligned.m8n8.x4.shared.b16 {%0,%1,%2,%3}, [%4];"
                 : "=r"(r[0]), "=r"(r[1]), "=r"(r[2]), "=r"(r[3]) : "r"(addr));
}
__device__ __forceinline__ void mma_bf16(float* c, const uint32_t* a, const uint32_t* b) {
    asm volatile(
        "mma.sync.aligned.m16n8k16.row.col.f32.bf16.bf16.f32 "
        "{%0,%1,%2,%3}, {%4,%5,%6,%7}, {%8,%9}, {%0,%1,%2,%3};\n"
        : "+f"(c[0]), "+f"(c[1]), "+f"(c[2]), "+f"(c[3])
        : "r"(a[0]), "r"(a[1]), "r"(a[2]), "r"(a[3]), "r"(b[0]), "r"(b[1]));
}
__device__ __forceinline__ uint32_t cvt2(float x, float y) {
    uint32_t r;
    asm("cvt.rn.bf16x2.f32 %0, %1, %2;" : "=r"(r) : "f"(y), "f"(x));   // lo = x, hi = y
    return r;
}

// ---------------- W1 convert+transpose pre-kernel ----------------
__global__ void w1_prep_kernel(const float* __restrict__ W1) {
    const int i = blockIdx.x * blockDim.x + threadIdx.x;   // over 1792*128
    if (i >= 1792 * 128) return;
    const int k = i >> 7;          // 0..1791
    const int n = i & 127;
    const int f = k >> 6;          // chunk
    const int kk = k & 63;
    g_Wtb[(f * 128 + n) * ROWE + kk] = __float2bfloat16(W1[i]);
}

// ---------------- main fused kernel ----------------
__global__ void __launch_bounds__(THREADS, 1)
dlrm_fused4(const int* __restrict__ user_ids,
            const int* __restrict__ item_ids,
            const int* __restrict__ sparse_features,
            const float* __restrict__ user_emb,
            const float* __restrict__ item_emb,
            const float* __restrict__ sparse_tables,
            const float* __restrict__ b1g,
            const float* __restrict__ w2g,
            const float* __restrict__ b2g,
            float* __restrict__ out)
{
    extern __shared__ char smem_raw[];
    char* base = (char*)(((uintptr_t)smem_raw + 255) & ~(uintptr_t)255);
    const uint32_t sb   = smem_u32(base);
    const uint32_t a0   = sb + OFF_A;
    const uint32_t w0   = sb + OFF_W;
    int*   ids  = (int*)(base + OFF_IDS);
    float* b1s  = (float*)(base + OFF_B1);
    float* w2s  = (float*)(base + OFF_W2);
    float* part = (float*)(base + OFF_PART);
    const uint32_t mb_full  = sb + OFF_MBAR;          // STAGES x 8B
    const uint32_t mb_empty = mb_full + STAGES * 8;   // STAGES x 8B

    const int tid  = threadIdx.x;
    const int wid  = tid >> 5;
    const int lane = tid & 31;
    const int row0 = blockIdx.x * TILE_B;

    if (tid == 0) {
        #pragma unroll
        for (int s = 0; s < STAGES; s++) {
            // full: 128 producer-lane release-arrives + 1 expect_tx arrival (W bulk)
            mbar_init(mb_full + s * 8, 129);
            // empty: 16 consumer warps
            mbar_init(mb_empty + s * 8, 16);
        }
    }
    // stage ids / b1 / w2
    for (int i = tid; i < NCHUNK * TILE_B; i += THREADS) {
        const int f = i >> 7;
        const int r = i & 127;
        int v;
        if (f == 0)      v = user_ids[row0 + r];
        else if (f == 1) v = item_ids[row0 + r];
        else             v = sparse_features[(size_t)(row0 + r) * NUM_SPARSE + (f - 2)];
        ids[f * TILE_B + r] = v;
    }
    if (tid < 128) { b1s[tid] = b1g[tid]; w2s[tid] = w2g[tid]; }
    __syncthreads();

    if (wid >= 16) {
        // ======== 4 producer warps: gather fp32 -> cvt bf16 -> STS ========
        const int plane = tid - 512;          // 0..127
        const int q  = plane >> 2;            // quad id: base row
        const int ql = plane & 3;             // lane in quad: float4 segment
        int s = 0;
        uint32_t par = 1;                     // fresh-barrier wait passes with parity 1
        for (int f = 0; f < NCHUNK; f++) {
            mbar_wait(mb_empty + s * 8, par);
            const uint32_t fullb = mb_full + s * 8;
            if (plane == 0) {
                mbar_expect_tx(fullb, W_TILE_BYTES);
                bulk_g2s(w0 + s * W_TILE_BYTES, g_Wtb + (size_t)f * 128 * ROWE,
                         W_TILE_BYTES, fullb);
            }
            const float* tbl = (f == 0) ? user_emb
                             : (f == 1) ? item_emb
                             : sparse_tables + (size_t)(f - 2) * SPARSE_VOCAB * 64;
            const uint32_t aS = a0 + s * A_TILE_BYTES;
            #pragma unroll
            for (int t = 0; t < 4; t++) {
                const int row = q + 32 * t;
                const int idx = ids[f * TILE_B + row];
                const float4* src = (const float4*)(tbl + (size_t)idx * 64);
                #pragma unroll
                for (int j = 0; j < 4; j++) {
                    const float4 v = __ldg(&src[ql + 4 * j]);
                    sts64(aS + row * ROWB + (ql + 4 * j) * 8,
                          cvt2(v.x, v.y), cvt2(v.z, v.w));
                }
            }
            mbar_arrive(fullb);               // release: my STS are visible
            if (++s == STAGES) { s = 0; par ^= 1; }
        }
    } else {
        // ======== 16 consumer warps: 32x32 tiles, bf16 m16n8k16 ========
        const int wm = (wid & 3) * 32;        // M offset (batch rows)
        const int wn = (wid >> 2) * 32;       // N offset (hidden cols)
        const int g   = lane >> 2;
        const int tig = lane & 3;

        const uint32_t aRow   = wm + (lane & 15);
        const uint32_t aCol16 = (lane >> 4) * 16;
        const uint32_t bRow   = wn + (lane & 7) + ((lane >> 4) << 3);
        const uint32_t bCol16 = ((lane >> 3) & 1) * 16;

        float acc[2][4][4];
        #pragma unroll
        for (int mt = 0; mt < 2; mt++)
            #pragma unroll
            for (int nt = 0; nt < 4; nt++)
                #pragma unroll
                for (int i = 0; i < 4; i++) acc[mt][nt][i] = 0.0f;

        int s = 0;
        uint32_t par = 0;
        for (int f = 0; f < NCHUNK; f++) {
            mbar_wait(mb_full + s * 8, par);
            const uint32_t aBase = a0 + s * A_TILE_BYTES + aRow * ROWB + aCol16;
            const uint32_t bBase = w0 + s * W_TILE_BYTES + bRow * ROWB + bCol16;

            #pragma unroll
            for (int it = 0; it < 4; it++) {           // K = 64 = 4 x k16
                uint32_t aa[2][4];
                uint32_t bb[2][4];
                ldm4(aa[0], aBase + it * 32);
                ldm4(aa[1], aBase + 16 * ROWB + it * 32);
                ldm4(bb[0], bBase + it * 32);          // n-tiles 0,1
                ldm4(bb[1], bBase + 16 * ROWB + it * 32);  // n-tiles 2,3
                #pragma unroll
                for (int mt = 0; mt < 2; mt++)
                    #pragma unroll
                    for (int q2 = 0; q2 < 2; q2++) {
                        mma_bf16(acc[mt][q2 * 2 + 0], aa[mt], &bb[q2][0]);
                        mma_bf16(acc[mt][q2 * 2 + 1], aa[mt], &bb[q2][2]);
                    }
            }
            if (lane == 0) mbar_arrive(mb_empty + s * 8);
            if (++s == STAGES) { s = 0; par ^= 1; }
        }

        // epilogue: bias + relu + dot(W2) partials over this warp's 32 cols
        #pragma unroll
        for (int mt = 0; mt < 2; mt++) {
            float p0 = 0.0f, p1 = 0.0f;
            #pragma unroll
            for (int nt = 0; nt < 4; nt++) {
                const int col = wn + nt * 8 + 2 * tig;
                const float b1a = b1s[col], b1b = b1s[col + 1];
                const float w2a = w2s[col], w2b = w2s[col + 1];
                p0 += fmaxf(acc[mt][nt][0] + b1a, 0.0f) * w2a
                    + fmaxf(acc[mt][nt][1] + b1b, 0.0f) * w2b;
                p1 += fmaxf(acc[mt][nt][2] + b1a, 0.0f) * w2a
                    + fmaxf(acc[mt][nt][3] + b1b, 0.0f) * w2b;
            }
            p0 += __shfl_xor_sync(0xffffffffu, p0, 1);
            p0 += __shfl_xor_sync(0xffffffffu, p0, 2);
            p1 += __shfl_xor_sync(0xffffffffu, p1, 1);
            p1 += __shfl_xor_sync(0xffffffffu, p1, 2);
            if (tig == 0) {
                const int grp = wid >> 2;            // column quarter
                part[grp * 128 + wm + mt * 16 + g]     = p0;
                part[grp * 128 + wm + mt * 16 + g + 8] = p1;
            }
        }
    }
    __syncthreads();

    if (tid < TILE_B) {
        const float raw = part[tid] + part[128 + tid] + part[256 + tid] + part[384 + tid]
                        + b2g[0];
        out[row0 + tid] = 1.0f / (1.0f + __expf(-raw));
    }
}

// ---------------- host ----------------
extern "C" void kernel_launch(void* const* d_in, const int* in_sizes, int n_in,
                              void* d_out, int out_size)
{
    const int*   user_ids        = (const int*)d_in[0];
    const int*   item_ids        = (const int*)d_in[1];
    const int*   sparse_features = (const int*)d_in[2];
    const float* user_emb        = (const float*)d_in[3];
    const float* item_emb        = (const float*)d_in[4];
    const float* sparse_tables   = (const float*)d_in[5];
    const float* W1              = (const float*)d_in[6];
    const float* b1              = (const float*)d_in[7];
    const float* W2              = (const float*)d_in[8];
    const float* b2              = (const float*)d_in[9];
    float*       out             = (float*)d_out;

    // pre-convert W1 into chunk-blocked padded bf16 transposed scratch
    w1_prep_kernel<<<(1792 * 128 + 255) / 256, 256>>>(W1);

    cudaFuncSetAttribute(dlrm_fused4,
                         cudaFuncAttributeMaxDynamicSharedMemorySize, SMEM_DYN);
    dlrm_fused4<<<16384 / TILE_B, THREADS, SMEM_DYN>>>(
        user_ids, item_ids, sparse_features,
        user_emb, item_emb, sparse_tables,
        b1, W2, b2, out);
}

// round 8
// speedup vs baseline: 1.5489x; 1.5489x over previous
#include <cuda_runtime.h>
#include <cuda_bf16.h>
#include <cstdint>

// ---------------- problem constants ----------------
#define NUM_SPARSE   26
#define NCHUNK       28           // user + item + 26 sparse, K=64 each
#define TILE_B       128
#define STAGES       5
#define SPARSE_VOCAB 100000
#define THREADS      640          // 16 consumer warps + 4 producer warps

// bf16 rows: 64 bf16 = 128B, XOR-swizzled in 16B blocks: blk' = blk ^ (row&7)
#define ROWB 128
#define A_TILE_BYTES (TILE_B * ROWB)     // 16384
#define W_TILE_BYTES (128 * ROWB)        // 16384

// smem offsets (from 256-aligned base)
#define OFF_A    0
#define OFF_W    (STAGES * A_TILE_BYTES)                  // 81920
#define OFF_IDS  (OFF_W + STAGES * W_TILE_BYTES)          // 163840
#define OFF_B1   (OFF_IDS + NCHUNK * TILE_B * 4)          // 178176
#define OFF_W2   (OFF_B1 + 512)                           // 178688
#define OFF_PART (OFF_W2 + 512)                           // 179200 (512 f32)
#define OFF_MBAR (OFF_PART + 2048)                        // 181248 (10 x 8B)
#define SMEM_USED (OFF_MBAR + 128)
#define SMEM_DYN  (SMEM_USED + 256)                       // ~181.6 KB

// W1 bf16 transposed + pre-swizzled scratch: [chunk][n=128][64 bf16]
__device__ __align__(256) __nv_bfloat16 g_Wtb[NCHUNK * 128 * 64];

// ---------------- helpers ----------------
__device__ __forceinline__ uint32_t smem_u32(const void* p) {
    uint32_t a;
    asm("{ .reg .u64 t; cvta.to.shared.u64 t, %1; cvt.u32.u64 %0, t; }" : "=r"(a) : "l"(p));
    return a;
}
__device__ __forceinline__ void mbar_init(uint32_t m, uint32_t cnt) {
    asm volatile("mbarrier.init.shared.b64 [%0], %1;" :: "r"(m), "r"(cnt) : "memory");
}
__device__ __forceinline__ void mbar_expect_tx(uint32_t m, uint32_t bytes) {
    asm volatile("mbarrier.arrive.expect_tx.shared.b64 _, [%0], %1;" :: "r"(m), "r"(bytes) : "memory");
}
__device__ __forceinline__ void mbar_arrive(uint32_t m) {
    asm volatile("mbarrier.arrive.release.cta.shared::cta.b64 _, [%0];" :: "r"(m) : "memory");
}
__device__ __forceinline__ void mbar_wait(uint32_t m, uint32_t parity) {
    asm volatile(
        "{\n\t.reg .pred P;\n\t"
        "W%=:\n\t"
        "mbarrier.try_wait.parity.acquire.cta.shared::cta.b64 P, [%0], %1, 0x989680;\n\t"
        "@!P bra W%=;\n\t}"
        :: "r"(m), "r"(parity) : "memory");
}
__device__ __forceinline__ void bulk_g2s(uint32_t dst, const void* src, uint32_t bytes,
                                         uint32_t mbar) {
    asm volatile(
        "cp.async.bulk.shared::cluster.global.mbarrier::complete_tx::bytes [%0], [%1], %2, [%3];"
        :: "r"(dst), "l"(src), "r"(bytes), "r"(mbar) : "memory");
}
__device__ __forceinline__ void sts128(uint32_t addr, uint32_t r0, uint32_t r1,
                                       uint32_t r2, uint32_t r3) {
    asm volatile("st.shared.v4.u32 [%0], {%1, %2, %3, %4};"
                 :: "r"(addr), "r"(r0), "r"(r1), "r"(r2), "r"(r3) : "memory");
}
__device__ __forceinline__ void ldm4(uint32_t* r, uint32_t addr) {
    asm volatile("ldmatrix.sync.aligned.m8n8.x4.shared.b16 {%0,%1,%2,%3}, [%4];"
                 : "=r"(r[0]), "=r"(r[1]), "=r"(r[2]), "=r"(r[3]) : "r"(addr));
}
__device__ __forceinline__ void mma_bf16(float* c, const uint32_t* a, const uint32_t* b) {
    asm volatile(
        "mma.sync.aligned.m16n8k16.row.col.f32.bf16.bf16.f32 "
        "{%0,%1,%2,%3}, {%4,%5,%6,%7}, {%8,%9}, {%0,%1,%2,%3};\n"
        : "+f"(c[0]), "+f"(c[1]), "+f"(c[2]), "+f"(c[3])
        : "r"(a[0]), "r"(a[1]), "r"(a[2]), "r"(a[3]), "r"(b[0]), "r"(b[1]));
}
__device__ __forceinline__ uint32_t cvt2(float x, float y) {
    uint32_t r;
    asm("cvt.rn.bf16x2.f32 %0, %1, %2;" : "=r"(r) : "f"(y), "f"(x));   // lo = x, hi = y
    return r;
}

// ---------------- W1 convert+transpose+swizzle pre-kernel ----------------
__global__ void w1_prep_kernel(const float* __restrict__ W1) {
    const int i = blockIdx.x * blockDim.x + threadIdx.x;   // over 1792*128
    if (i >= 1792 * 128) return;
    const int k = i >> 7;          // 0..1791
    const int n = i & 127;
    const int f = k >> 6;          // chunk
    const int kk = k & 63;         // k within chunk
    const int blk = kk >> 3;       // 16B block (8 bf16)
    const int within = kk & 7;
    const int sblk = blk ^ (n & 7);
    g_Wtb[((size_t)(f * 128 + n) << 6) + (sblk << 3) + within] = __float2bfloat16(W1[i]);
}

// ---------------- main fused kernel ----------------
__global__ void __launch_bounds__(THREADS, 1)
dlrm_fused5(const int* __restrict__ user_ids,
            const int* __restrict__ item_ids,
            const int* __restrict__ sparse_features,
            const float* __restrict__ user_emb,
            const float* __restrict__ item_emb,
            const float* __restrict__ sparse_tables,
            const float* __restrict__ b1g,
            const float* __restrict__ w2g,
            const float* __restrict__ b2g,
            float* __restrict__ out)
{
    extern __shared__ char smem_raw[];
    char* base = (char*)(((uintptr_t)smem_raw + 255) & ~(uintptr_t)255);
    const uint32_t sb   = smem_u32(base);
    const uint32_t a0   = sb + OFF_A;
    const uint32_t w0   = sb + OFF_W;
    int*   ids  = (int*)(base + OFF_IDS);
    float* b1s  = (float*)(base + OFF_B1);
    float* w2s  = (float*)(base + OFF_W2);
    float* part = (float*)(base + OFF_PART);
    const uint32_t mb_full  = sb + OFF_MBAR;          // STAGES x 8B
    const uint32_t mb_empty = mb_full + STAGES * 8;   // STAGES x 8B

    const int tid  = threadIdx.x;
    const int wid  = tid >> 5;
    const int lane = tid & 31;
    const int row0 = blockIdx.x * TILE_B;

    if (tid == 0) {
        #pragma unroll
        for (int s = 0; s < STAGES; s++) {
            // full: 128 producer-lane release-arrives + 1 expect_tx arrival (W bulk)
            mbar_init(mb_full + s * 8, 129);
            // empty: 16 consumer warps
            mbar_init(mb_empty + s * 8, 16);
        }
    }
    // stage ids / b1 / w2
    for (int i = tid; i < NCHUNK * TILE_B; i += THREADS) {
        const int f = i >> 7;
        const int r = i & 127;
        int v;
        if (f == 0)      v = user_ids[row0 + r];
        else if (f == 1) v = item_ids[row0 + r];
        else             v = sparse_features[(size_t)(row0 + r) * NUM_SPARSE + (f - 2)];
        ids[f * TILE_B + r] = v;
    }
    if (tid < 128) { b1s[tid] = b1g[tid]; w2s[tid] = w2g[tid]; }
    __syncthreads();

    if (wid >= 16) {
        // ======== 4 producer warps, software-pipelined gather+cvt ========
        const int plane = tid - 512;          // 0..127: one row per lane
        const int rx = plane & 7;             // swizzle xor for this row

        float4 v[16];                         // one full fp32 row in flight
        {
            const int idx = ids[plane];       // chunk 0 (user)
            const float4* src = (const float4*)(user_emb + (size_t)idx * 64);
            #pragma unroll
            for (int j = 0; j < 16; j++) v[j] = __ldg(src + j);
        }

        int s = 0;
        uint32_t par = 1;                     // fresh-barrier wait passes with parity 1
        for (int f = 0; f < NCHUNK; f++) {
            mbar_wait(mb_empty + s * 8, par);
            const uint32_t fullb = mb_full + s * 8;
            if (plane == 0) {
                mbar_expect_tx(fullb, W_TILE_BYTES);
                bulk_g2s(w0 + s * W_TILE_BYTES, g_Wtb + ((size_t)f << 13),
                         W_TILE_BYTES, fullb);
            }
            // store current row (cvt fp32 -> bf16), swizzled 16B blocks
            const uint32_t rowb = a0 + s * A_TILE_BYTES + plane * ROWB;
            #pragma unroll
            for (int j2 = 0; j2 < 8; j2++) {
                sts128(rowb + ((j2 ^ rx) << 4),
                       cvt2(v[2 * j2].x,     v[2 * j2].y),
                       cvt2(v[2 * j2].z,     v[2 * j2].w),
                       cvt2(v[2 * j2 + 1].x, v[2 * j2 + 1].y),
                       cvt2(v[2 * j2 + 1].z, v[2 * j2 + 1].w));
            }
            mbar_arrive(fullb);               // release: my STS are visible

            // prefetch next chunk's row into registers (latency overlaps waits)
            if (f + 1 < NCHUNK) {
                const int fn = f + 1;
                const float* tbl = (fn == 1) ? item_emb
                                 : sparse_tables + (size_t)(fn - 2) * SPARSE_VOCAB * 64;
                const int idx = ids[fn * TILE_B + plane];
                const float4* src = (const float4*)(tbl + (size_t)idx * 64);
                #pragma unroll
                for (int j = 0; j < 16; j++) v[j] = __ldg(src + j);
            }
            if (++s == STAGES) { s = 0; par ^= 1; }
        }
    } else {
        // ======== 16 consumer warps: 32x32 tiles, bf16 m16n8k16 ========
        const int wm = (wid & 3) * 32;        // M offset (batch rows)
        const int wn = (wid >> 2) * 32;       // N offset (hidden cols)
        const int g   = lane >> 2;
        const int tig = lane & 3;

        const uint32_t aRow = wm + (lane & 15);
        const uint32_t aHi  = lane >> 4;          // which 8-bf16 half of k16
        const uint32_t axor = aRow & 7;
        const uint32_t bRow = wn + (lane & 7) + ((lane >> 4) << 3);
        const uint32_t bHi  = (lane >> 3) & 1;
        const uint32_t bxor = bRow & 7;

        float acc[2][4][4];
        #pragma unroll
        for (int mt = 0; mt < 2; mt++)
            #pragma unroll
            for (int nt = 0; nt < 4; nt++)
                #pragma unroll
                for (int i = 0; i < 4; i++) acc[mt][nt][i] = 0.0f;

        int s = 0;
        uint32_t par = 0;
        for (int f = 0; f < NCHUNK; f++) {
            mbar_wait(mb_full + s * 8, par);
            const uint32_t aRowAddr = a0 + s * A_TILE_BYTES + aRow * ROWB;
            const uint32_t bRowAddr = w0 + s * W_TILE_BYTES + bRow * ROWB;

            #pragma unroll
            for (int it = 0; it < 4; it++) {           // K = 64 = 4 x k16
                uint32_t aa[2][4];
                uint32_t bb[2][4];
                const uint32_t blkA = ((it * 2 + aHi) ^ axor) << 4;
                const uint32_t blkB = ((it * 2 + bHi) ^ bxor) << 4;
                ldm4(aa[0], aRowAddr + blkA);
                ldm4(aa[1], aRowAddr + 16 * ROWB + blkA);
                ldm4(bb[0], bRowAddr + blkB);              // n-tiles 0,1
                ldm4(bb[1], bRowAddr + 16 * ROWB + blkB);  // n-tiles 2,3
                #pragma unroll
                for (int mt = 0; mt < 2; mt++)
                    #pragma unroll
                    for (int q2 = 0; q2 < 2; q2++) {
                        mma_bf16(acc[mt][q2 * 2 + 0], aa[mt], &bb[q2][0]);
                        mma_bf16(acc[mt][q2 * 2 + 1], aa[mt], &bb[q2][2]);
                    }
            }
            if (lane == 0) mbar_arrive(mb_empty + s * 8);
            if (++s == STAGES) { s = 0; par ^= 1; }
        }

        // epilogue: bias + relu + dot(W2) partials over this warp's 32 cols
        #pragma unroll
        for (int mt = 0; mt < 2; mt++) {
            float p0 = 0.0f, p1 = 0.0f;
            #pragma unroll
            for (int nt = 0; nt < 4; nt++) {
                const int col = wn + nt * 8 + 2 * tig;
                const float b1a = b1s[col], b1b = b1s[col + 1];
                const float w2a = w2s[col], w2b = w2s[col + 1];
                p0 += fmaxf(acc[mt][nt][0] + b1a, 0.0f) * w2a
                    + fmaxf(acc[mt][nt][1] + b1b, 0.0f) * w2b;
                p1 += fmaxf(acc[mt][nt][2] + b1a, 0.0f) * w2a
                    + fmaxf(acc[mt][nt][3] + b1b, 0.0f) * w2b;
            }
            p0 += __shfl_xor_sync(0xffffffffu, p0, 1);
            p0 += __shfl_xor_sync(0xffffffffu, p0, 2);
            p1 += __shfl_xor_sync(0xffffffffu, p1, 1);
            p1 += __shfl_xor_sync(0xffffffffu, p1, 2);
            if (tig == 0) {
                const int grp = wid >> 2;            // column quarter
                part[grp * 128 + wm + mt * 16 + g]     = p0;
                part[grp * 128 + wm + mt * 16 + g + 8] = p1;
            }
        }
    }
    __syncthreads();

    if (tid < TILE_B) {
        const float raw = part[tid] + part[128 + tid] + part[256 + tid] + part[384 + tid]
                        + b2g[0];
        out[row0 + tid] = 1.0f / (1.0f + __expf(-raw));
    }
}

// ---------------- host ----------------
extern "C" void kernel_launch(void* const* d_in, const int* in_sizes, int n_in,
                              void* d_out, int out_size)
{
    const int*   user_ids        = (const int*)d_in[0];
    const int*   item_ids        = (const int*)d_in[1];
    const int*   sparse_features = (const int*)d_in[2];
    const float* user_emb        = (const float*)d_in[3];
    const float* item_emb        = (const float*)d_in[4];
    const float* sparse_tables   = (const float*)d_in[5];
    const float* W1              = (const float*)d_in[6];
    const float* b1              = (const float*)d_in[7];
    const float* W2              = (const float*)d_in[8];
    const float* b2              = (const float*)d_in[9];
    float*       out             = (float*)d_out;

    // pre-convert W1 into chunk-blocked, transposed, pre-swizzled bf16 scratch
    w1_prep_kernel<<<(1792 * 128 + 255) / 256, 256>>>(W1);

    cudaFuncSetAttribute(dlrm_fused5,
                         cudaFuncAttributeMaxDynamicSharedMemorySize, SMEM_DYN);
    dlrm_fused5<<<16384 / TILE_B, THREADS, SMEM_DYN>>>(
        user_ids, item_ids, sparse_features,
        user_emb, item_emb, sparse_tables,
        b1, W2, b2, out);
}

// round 9
// speedup vs baseline: 2.0127x; 1.2995x over previous
#include <cuda_runtime.h>
#include <cuda_bf16.h>
#include <cstdint>

// ---------------- problem constants ----------------
#define NUM_SPARSE   26
#define NCHUNK       28           // user + item + 26 sparse, K=64 each
#define TILE_B       128
#define STAGES       5
#define SPARSE_VOCAB 100000
#define THREADS      640          // 16 consumer warps + 4 producer warps

// bf16 rows: 64 bf16 = 128B, XOR-swizzled in 16B blocks: blk' = blk ^ (row&7)
#define ROWB 128
#define A_TILE_BYTES (TILE_B * ROWB)     // 16384
#define W_TILE_BYTES (128 * ROWB)        // 16384

// smem offsets (from 256-aligned base)
#define OFF_A    0
#define OFF_W    (STAGES * A_TILE_BYTES)                  // 81920
#define OFF_IDS  (OFF_W + STAGES * W_TILE_BYTES)          // 163840
#define OFF_B1   (OFF_IDS + NCHUNK * TILE_B * 4)          // 178176
#define OFF_W2   (OFF_B1 + 512)                           // 178688
#define OFF_PART (OFF_W2 + 512)                           // 179200 (512 f32)
#define OFF_MBAR (OFF_PART + 2048)                        // 181248 (10 x 8B)
#define SMEM_USED (OFF_MBAR + 128)
#define SMEM_DYN  (SMEM_USED + 256)                       // ~181.6 KB

// W1 bf16 transposed + pre-swizzled scratch: [chunk][n=128][64 bf16]
__device__ __align__(256) __nv_bfloat16 g_Wtb[NCHUNK * 128 * 64];

// ---------------- helpers ----------------
__device__ __forceinline__ uint32_t smem_u32(const void* p) {
    uint32_t a;
    asm("{ .reg .u64 t; cvta.to.shared.u64 t, %1; cvt.u32.u64 %0, t; }" : "=r"(a) : "l"(p));
    return a;
}
__device__ __forceinline__ void mbar_init(uint32_t m, uint32_t cnt) {
    asm volatile("mbarrier.init.shared.b64 [%0], %1;" :: "r"(m), "r"(cnt) : "memory");
}
__device__ __forceinline__ void mbar_expect_tx(uint32_t m, uint32_t bytes) {
    asm volatile("mbarrier.arrive.expect_tx.shared.b64 _, [%0], %1;" :: "r"(m), "r"(bytes) : "memory");
}
__device__ __forceinline__ void mbar_arrive(uint32_t m) {
    asm volatile("mbarrier.arrive.release.cta.shared::cta.b64 _, [%0];" :: "r"(m) : "memory");
}
__device__ __forceinline__ void mbar_wait(uint32_t m, uint32_t parity) {
    asm volatile(
        "{\n\t.reg .pred P;\n\t"
        "W%=:\n\t"
        "mbarrier.try_wait.parity.acquire.cta.shared::cta.b64 P, [%0], %1, 0x989680;\n\t"
        "@!P bra W%=;\n\t}"
        :: "r"(m), "r"(parity) : "memory");
}
__device__ __forceinline__ void bulk_g2s(uint32_t dst, const void* src, uint32_t bytes,
                                         uint32_t mbar) {
    asm volatile(
        "cp.async.bulk.shared::cluster.global.mbarrier::complete_tx::bytes [%0], [%1], %2, [%3];"
        :: "r"(dst), "l"(src), "r"(bytes), "r"(mbar) : "memory");
}
__device__ __forceinline__ void sts64(uint32_t addr, uint32_t p0, uint32_t p1) {
    asm volatile("st.shared.v2.u32 [%0], {%1, %2};" :: "r"(addr), "r"(p0), "r"(p1) : "memory");
}
__device__ __forceinline__ void ldm4(uint32_t* r, uint32_t addr) {
    asm volatile("ldmatrix.sync.aligned.m8n8.x4.shared.b16 {%0,%1,%2,%3}, [%4];"
                 : "=r"(r[0]), "=r"(r[1]), "=r"(r[2]), "=r"(r[3]) : "r"(addr));
}
__device__ __forceinline__ void mma_bf16(float* c, const uint32_t* a, const uint32_t* b) {
    asm volatile(
        "mma.sync.aligned.m16n8k16.row.col.f32.bf16.bf16.f32 "
        "{%0,%1,%2,%3}, {%4,%5,%6,%7}, {%8,%9}, {%0,%1,%2,%3};\n"
        : "+f"(c[0]), "+f"(c[1]), "+f"(c[2]), "+f"(c[3])
        : "r"(a[0]), "r"(a[1]), "r"(a[2]), "r"(a[3]), "r"(b[0]), "r"(b[1]));
}
__device__ __forceinline__ uint32_t cvt2(float x, float y) {
    uint32_t r;
    asm("cvt.rn.bf16x2.f32 %0, %1, %2;" : "=r"(r) : "f"(y), "f"(x));   // lo = x, hi = y
    return r;
}

// ---------------- W1 convert+transpose+swizzle pre-kernel ----------------
__global__ void w1_prep_kernel(const float* __restrict__ W1) {
    const int i = blockIdx.x * blockDim.x + threadIdx.x;   // over 1792*128
    if (i >= 1792 * 128) return;
    const int k = i >> 7;          // 0..1791
    const int n = i & 127;
    const int f = k >> 6;          // chunk
    const int kk = k & 63;         // k within chunk
    const int blk = kk >> 3;       // 16B block (8 bf16)
    const int within = kk & 7;
    const int sblk = blk ^ (n & 7);
    g_Wtb[((size_t)(f * 128 + n) << 6) + (sblk << 3) + within] = __float2bfloat16(W1[i]);
}

// ---------------- main fused kernel ----------------
__global__ void __launch_bounds__(THREADS, 1)
dlrm_fused6(const int* __restrict__ user_ids,
            const int* __restrict__ item_ids,
            const int* __restrict__ sparse_features,
            const float* __restrict__ user_emb,
            const float* __restrict__ item_emb,
            const float* __restrict__ sparse_tables,
            const float* __restrict__ b1g,
            const float* __restrict__ w2g,
            const float* __restrict__ b2g,
            float* __restrict__ out)
{
    extern __shared__ char smem_raw[];
    char* base = (char*)(((uintptr_t)smem_raw + 255) & ~(uintptr_t)255);
    const uint32_t sb   = smem_u32(base);
    const uint32_t a0   = sb + OFF_A;
    const uint32_t w0   = sb + OFF_W;
    int*   ids  = (int*)(base + OFF_IDS);
    float* b1s  = (float*)(base + OFF_B1);
    float* w2s  = (float*)(base + OFF_W2);
    float* part = (float*)(base + OFF_PART);
    const uint32_t mb_full  = sb + OFF_MBAR;          // STAGES x 8B
    const uint32_t mb_empty = mb_full + STAGES * 8;   // STAGES x 8B

    const int tid  = threadIdx.x;
    const int wid  = tid >> 5;
    const int lane = tid & 31;
    const int row0 = blockIdx.x * TILE_B;

    if (tid == 0) {
        #pragma unroll
        for (int s = 0; s < STAGES; s++) {
            // full: 128 producer-lane release-arrives + 1 expect_tx arrival (W bulk)
            mbar_init(mb_full + s * 8, 129);
            // empty: 16 consumer warps
            mbar_init(mb_empty + s * 8, 16);
        }
    }
    // stage ids / b1 / w2
    for (int i = tid; i < NCHUNK * TILE_B; i += THREADS) {
        const int f = i >> 7;
        const int r = i & 127;
        int v;
        if (f == 0)      v = user_ids[row0 + r];
        else if (f == 1) v = item_ids[row0 + r];
        else             v = sparse_features[(size_t)(row0 + r) * NUM_SPARSE + (f - 2)];
        ids[f * TILE_B + r] = v;
    }
    if (tid < 128) { b1s[tid] = b1g[tid]; w2s[tid] = w2g[tid]; }
    __syncthreads();

    if (wid >= 16) {
        // ===== 4 producer warps: 8 lanes/row coalesced gather + cvt =====
        // lane 'plane' owns fp32 16B-segments {s8, s8+8} of rows rbase+16*r (r=0..7).
        // Each LDG.128 instruction: 4 rows x one aligned 128B line -> nL=4.
        const int plane = tid - 512;          // 0..127
        const int s8    = plane & 7;          // fp32 segment id (16B units)
        const int rbase = plane >> 3;         // 0..15
        const int rx    = rbase & 7;          // row swizzle xor (invariant: (rbase+16r)&7)

        // swizzled byte offsets within a 128B bf16 row for segments s8 and s8+8
        const uint32_t off0 = (uint32_t)(((s8 >> 1) ^ rx) << 4) + ((s8 & 1) << 3);
        const uint32_t off1 = (uint32_t)((((s8 >> 1) + 4) ^ rx) << 4) + ((s8 & 1) << 3);

        float4 v[16];                         // 8 rows x 2 segments in flight
        {
            #pragma unroll
            for (int r = 0; r < 8; r++) {
                const int idx = ids[rbase + 16 * r];          // chunk 0 (user)
                const float4* src = (const float4*)(user_emb + (size_t)idx * 64);
                v[2 * r]     = __ldg(src + s8);
                v[2 * r + 1] = __ldg(src + s8 + 8);
            }
        }

        int s = 0;
        uint32_t par = 1;                     // fresh-barrier wait passes with parity 1
        for (int f = 0; f < NCHUNK; f++) {
            mbar_wait(mb_empty + s * 8, par);
            const uint32_t fullb = mb_full + s * 8;
            if (plane == 0) {
                mbar_expect_tx(fullb, W_TILE_BYTES);
                bulk_g2s(w0 + s * W_TILE_BYTES, g_Wtb + ((size_t)f << 13),
                         W_TILE_BYTES, fullb);
            }
            const uint32_t aS = a0 + s * A_TILE_BYTES;
            #pragma unroll
            for (int r = 0; r < 8; r++) {
                const uint32_t rowb = aS + (uint32_t)(rbase + 16 * r) * ROWB;
                sts64(rowb + off0, cvt2(v[2 * r].x,     v[2 * r].y),
                                   cvt2(v[2 * r].z,     v[2 * r].w));
                sts64(rowb + off1, cvt2(v[2 * r + 1].x, v[2 * r + 1].y),
                                   cvt2(v[2 * r + 1].z, v[2 * r + 1].w));
            }
            mbar_arrive(fullb);               // release: my STS are visible

            // prefetch next chunk's segments (latency overlaps waits/compute)
            if (f + 1 < NCHUNK) {
                const int fn = f + 1;
                const float* tbl = (fn == 1) ? item_emb
                                 : sparse_tables + (size_t)(fn - 2) * SPARSE_VOCAB * 64;
                #pragma unroll
                for (int r = 0; r < 8; r++) {
                    const int idx = ids[fn * TILE_B + rbase + 16 * r];
                    const float4* src = (const float4*)(tbl + (size_t)idx * 64);
                    v[2 * r]     = __ldg(src + s8);
                    v[2 * r + 1] = __ldg(src + s8 + 8);
                }
            }
            if (++s == STAGES) { s = 0; par ^= 1; }
        }
    } else {
        // ======== 16 consumer warps: 32x32 tiles, bf16 m16n8k16 ========
        const int wm = (wid & 3) * 32;        // M offset (batch rows)
        const int wn = (wid >> 2) * 32;       // N offset (hidden cols)
        const int g   = lane >> 2;
        const int tig = lane & 3;

        const uint32_t aRow = wm + (lane & 15);
        const uint32_t aHi  = lane >> 4;          // which 8-bf16 half of k16
        const uint32_t axor = aRow & 7;
        const uint32_t bRow = wn + (lane & 7) + ((lane >> 4) << 3);
        const uint32_t bHi  = (lane >> 3) & 1;
        const uint32_t bxor = bRow & 7;

        float acc[2][4][4];
        #pragma unroll
        for (int mt = 0; mt < 2; mt++)
            #pragma unroll
            for (int nt = 0; nt < 4; nt++)
                #pragma unroll
                for (int i = 0; i < 4; i++) acc[mt][nt][i] = 0.0f;

        int s = 0;
        uint32_t par = 0;
        for (int f = 0; f < NCHUNK; f++) {
            mbar_wait(mb_full + s * 8, par);
            const uint32_t aRowAddr = a0 + s * A_TILE_BYTES + aRow * ROWB;
            const uint32_t bRowAddr = w0 + s * W_TILE_BYTES + bRow * ROWB;

            #pragma unroll
            for (int it = 0; it < 4; it++) {           // K = 64 = 4 x k16
                uint32_t aa[2][4];
                uint32_t bb[2][4];
                const uint32_t blkA = ((it * 2 + aHi) ^ axor) << 4;
                const uint32_t blkB = ((it * 2 + bHi) ^ bxor) << 4;
                ldm4(aa[0], aRowAddr + blkA);
                ldm4(aa[1], aRowAddr + 16 * ROWB + blkA);
                ldm4(bb[0], bRowAddr + blkB);              // n-tiles 0,1
                ldm4(bb[1], bRowAddr + 16 * ROWB + blkB);  // n-tiles 2,3
                #pragma unroll
                for (int mt = 0; mt < 2; mt++)
                    #pragma unroll
                    for (int q2 = 0; q2 < 2; q2++) {
                        mma_bf16(acc[mt][q2 * 2 + 0], aa[mt], &bb[q2][0]);
                        mma_bf16(acc[mt][q2 * 2 + 1], aa[mt], &bb[q2][2]);
                    }
            }
            if (lane == 0) mbar_arrive(mb_empty + s * 8);
            if (++s == STAGES) { s = 0; par ^= 1; }
        }

        // epilogue: bias + relu + dot(W2) partials over this warp's 32 cols
        #pragma unroll
        for (int mt = 0; mt < 2; mt++) {
            float p0 = 0.0f, p1 = 0.0f;
            #pragma unroll
            for (int nt = 0; nt < 4; nt++) {
                const int col = wn + nt * 8 + 2 * tig;
                const float b1a = b1s[col], b1b = b1s[col + 1];
                const float w2a = w2s[col], w2b = w2s[col + 1];
                p0 += fmaxf(acc[mt][nt][0] + b1a, 0.0f) * w2a
                    + fmaxf(acc[mt][nt][1] + b1b, 0.0f) * w2b;
                p1 += fmaxf(acc[mt][nt][2] + b1a, 0.0f) * w2a
                    + fmaxf(acc[mt][nt][3] + b1b, 0.0f) * w2b;
            }
            p0 += __shfl_xor_sync(0xffffffffu, p0, 1);
            p0 += __shfl_xor_sync(0xffffffffu, p0, 2);
            p1 += __shfl_xor_sync(0xffffffffu, p1, 1);
            p1 += __shfl_xor_sync(0xffffffffu, p1, 2);
            if (tig == 0) {
                const int grp = wid >> 2;            // column quarter
                part[grp * 128 + wm + mt * 16 + g]     = p0;
                part[grp * 128 + wm + mt * 16 + g + 8] = p1;
            }
        }
    }
    __syncthreads();

    if (tid < TILE_B) {
        const float raw = part[tid] + part[128 + tid] + part[256 + tid] + part[384 + tid]
                        + b2g[0];
        out[row0 + tid] = 1.0f / (1.0f + __expf(-raw));
    }
}

// ---------------- host ----------------
extern "C" void kernel_launch(void* const* d_in, const int* in_sizes, int n_in,
                              void* d_out, int out_size)
{
    const int*   user_ids        = (const int*)d_in[0];
    const int*   item_ids        = (const int*)d_in[1];
    const int*   sparse_features = (const int*)d_in[2];
    const float* user_emb        = (const float*)d_in[3];
    const float* item_emb        = (const float*)d_in[4];
    const float* sparse_tables   = (const float*)d_in[5];
    const float* W1              = (const float*)d_in[6];
    const float* b1              = (const float*)d_in[7];
    const float* W2              = (const float*)d_in[8];
    const float* b2              = (const float*)d_in[9];
    float*       out             = (float*)d_out;

    // pre-convert W1 into chunk-blocked, transposed, pre-swizzled bf16 scratch
    w1_prep_kernel<<<(1792 * 128 + 255) / 256, 256>>>(W1);

    cudaFuncSetAttribute(dlrm_fused6,
                         cudaFuncAttributeMaxDynamicSharedMemorySize, SMEM_DYN);
    dlrm_fused6<<<16384 / TILE_B, THREADS, SMEM_DYN>>>(
        user_ids, item_ids, sparse_features,
        user_emb, item_emb, sparse_tables,
        b1, W2, b2, out);
}

// round 10
// speedup vs baseline: 2.2010x; 1.0936x over previous
#include <cuda_runtime.h>
#include <cuda_bf16.h>
#include <cstdint>

// ---------------- problem constants ----------------
#define NUM_SPARSE   26
#define NCHUNK       28           // user + item + 26 sparse, K=64 each
#define TILE_B       64
#define STAGES       4
#define SPARSE_VOCAB 100000
#define THREADS      320          // 8 consumer warps + 2 producer warps

// bf16 rows: 64 bf16 = 128B, XOR-swizzled in 16B blocks: blk' = blk ^ (row&7)
#define ROWB 128
#define A_TILE_BYTES (TILE_B * ROWB)     // 8192
#define W_TILE_BYTES (128 * ROWB)        // 16384

// smem offsets (from 256-aligned base)
#define OFF_A    0
#define OFF_W    (STAGES * A_TILE_BYTES)                  // 32768
#define OFF_IDS  (OFF_W + STAGES * W_TILE_BYTES)          // 98304
#define OFF_B1   (OFF_IDS + NCHUNK * TILE_B * 4)          // 105472
#define OFF_W2   (OFF_B1 + 512)                           // 105984
#define OFF_PART (OFF_W2 + 512)                           // 106496 (256 f32)
#define OFF_MBAR (OFF_PART + 1024)                        // 107520 (8 x 8B)
#define SMEM_USED (OFF_MBAR + 128)
#define SMEM_DYN  (SMEM_USED + 256)                       // ~107.9 KB -> 2 CTAs/SM

// W1 bf16 transposed + pre-swizzled scratch: [chunk][n=128][64 bf16]
__device__ __align__(256) __nv_bfloat16 g_Wtb[NCHUNK * 128 * 64];

// ---------------- helpers ----------------
__device__ __forceinline__ uint32_t smem_u32(const void* p) {
    uint32_t a;
    asm("{ .reg .u64 t; cvta.to.shared.u64 t, %1; cvt.u32.u64 %0, t; }" : "=r"(a) : "l"(p));
    return a;
}
__device__ __forceinline__ void mbar_init(uint32_t m, uint32_t cnt) {
    asm volatile("mbarrier.init.shared.b64 [%0], %1;" :: "r"(m), "r"(cnt) : "memory");
}
__device__ __forceinline__ void mbar_expect_tx(uint32_t m, uint32_t bytes) {
    asm volatile("mbarrier.arrive.expect_tx.shared.b64 _, [%0], %1;" :: "r"(m), "r"(bytes) : "memory");
}
__device__ __forceinline__ void mbar_arrive(uint32_t m) {
    asm volatile("mbarrier.arrive.release.cta.shared::cta.b64 _, [%0];" :: "r"(m) : "memory");
}
__device__ __forceinline__ void mbar_wait(uint32_t m, uint32_t parity) {
    asm volatile(
        "{\n\t.reg .pred P;\n\t"
        "W%=:\n\t"
        "mbarrier.try_wait.parity.acquire.cta.shared::cta.b64 P, [%0], %1, 0x989680;\n\t"
        "@!P bra W%=;\n\t}"
        :: "r"(m), "r"(parity) : "memory");
}
__device__ __forceinline__ void bulk_g2s(uint32_t dst, const void* src, uint32_t bytes,
                                         uint32_t mbar) {
    asm volatile(
        "cp.async.bulk.shared::cluster.global.mbarrier::complete_tx::bytes [%0], [%1], %2, [%3];"
        :: "r"(dst), "l"(src), "r"(bytes), "r"(mbar) : "memory");
}
__device__ __forceinline__ void sts64(uint32_t addr, uint32_t p0, uint32_t p1) {
    asm volatile("st.shared.v2.u32 [%0], {%1, %2};" :: "r"(addr), "r"(p0), "r"(p1) : "memory");
}
__device__ __forceinline__ void ldm4(uint32_t* r, uint32_t addr) {
    asm volatile("ldmatrix.sync.aligned.m8n8.x4.shared.b16 {%0,%1,%2,%3}, [%4];"
                 : "=r"(r[0]), "=r"(r[1]), "=r"(r[2]), "=r"(r[3]) : "r"(addr));
}
__device__ __forceinline__ void mma_bf16(float* c, const uint32_t* a, const uint32_t* b) {
    asm volatile(
        "mma.sync.aligned.m16n8k16.row.col.f32.bf16.bf16.f32 "
        "{%0,%1,%2,%3}, {%4,%5,%6,%7}, {%8,%9}, {%0,%1,%2,%3};\n"
        : "+f"(c[0]), "+f"(c[1]), "+f"(c[2]), "+f"(c[3])
        : "r"(a[0]), "r"(a[1]), "r"(a[2]), "r"(a[3]), "r"(b[0]), "r"(b[1]));
}
__device__ __forceinline__ uint32_t cvt2(float x, float y) {
    uint32_t r;
    asm("cvt.rn.bf16x2.f32 %0, %1, %2;" : "=r"(r) : "f"(y), "f"(x));   // lo = x, hi = y
    return r;
}

// ---------------- W1 convert+transpose+swizzle pre-kernel ----------------
__global__ void w1_prep_kernel(const float* __restrict__ W1) {
    const int i = blockIdx.x * blockDim.x + threadIdx.x;   // over 1792*128
    if (i >= 1792 * 128) return;
    const int k = i >> 7;          // 0..1791
    const int n = i & 127;
    const int f = k >> 6;          // chunk
    const int kk = k & 63;         // k within chunk
    const int blk = kk >> 3;       // 16B block (8 bf16)
    const int within = kk & 7;
    const int sblk = blk ^ (n & 7);
    g_Wtb[((size_t)(f * 128 + n) << 6) + (sblk << 3) + within] = __float2bfloat16(W1[i]);
}

// ---------------- main fused kernel ----------------
__global__ void __launch_bounds__(THREADS, 2)
dlrm_fused7(const int* __restrict__ user_ids,
            const int* __restrict__ item_ids,
            const int* __restrict__ sparse_features,
            const float* __restrict__ user_emb,
            const float* __restrict__ item_emb,
            const float* __restrict__ sparse_tables,
            const float* __restrict__ b1g,
            const float* __restrict__ w2g,
            const float* __restrict__ b2g,
            float* __restrict__ out)
{
    extern __shared__ char smem_raw[];
    char* base = (char*)(((uintptr_t)smem_raw + 255) & ~(uintptr_t)255);
    const uint32_t sb   = smem_u32(base);
    const uint32_t a0   = sb + OFF_A;
    const uint32_t w0   = sb + OFF_W;
    int*   ids  = (int*)(base + OFF_IDS);
    float* b1s  = (float*)(base + OFF_B1);
    float* w2s  = (float*)(base + OFF_W2);
    float* part = (float*)(base + OFF_PART);
    const uint32_t mb_full  = sb + OFF_MBAR;          // STAGES x 8B
    const uint32_t mb_empty = mb_full + STAGES * 8;   // STAGES x 8B

    const int tid  = threadIdx.x;
    const int wid  = tid >> 5;
    const int lane = tid & 31;
    const int row0 = blockIdx.x * TILE_B;

    if (tid == 0) {
        #pragma unroll
        for (int s = 0; s < STAGES; s++) {
            // full: 64 producer-lane release-arrives + 1 expect_tx arrival (W bulk)
            mbar_init(mb_full + s * 8, 65);
            // empty: 8 consumer warps
            mbar_init(mb_empty + s * 8, 8);
        }
    }
    // stage ids / b1 / w2
    for (int i = tid; i < NCHUNK * TILE_B; i += THREADS) {
        const int f = i >> 6;
        const int r = i & 63;
        int v;
        if (f == 0)      v = user_ids[row0 + r];
        else if (f == 1) v = item_ids[row0 + r];
        else             v = sparse_features[(size_t)(row0 + r) * NUM_SPARSE + (f - 2)];
        ids[f * TILE_B + r] = v;
    }
    if (tid < 128) { b1s[tid] = b1g[tid]; w2s[tid] = w2g[tid]; }
    __syncthreads();

    if (wid >= 8) {
        // ===== 2 producer warps: 8 lanes/row coalesced gather + cvt =====
        // lane 'plane' owns fp32 16B-segments {s8, s8+8} of rows rbase+8*r (r=0..7).
        // Each LDG.128 instruction: 4 rows x one aligned 128B line -> nL=4.
        const int plane = tid - 256;          // 0..63
        const int s8    = plane & 7;          // fp32 segment id (16B units)
        const int rbase = plane >> 3;         // 0..7
        const int rx    = rbase;              // row swizzle xor ((rbase+8r)&7 = rbase)

        // swizzled byte offsets within a 128B bf16 row for segments s8 and s8+8
        const uint32_t off0 = (uint32_t)(((s8 >> 1) ^ rx) << 4) + ((s8 & 1) << 3);
        const uint32_t off1 = (uint32_t)((((s8 >> 1) + 4) ^ rx) << 4) + ((s8 & 1) << 3);

        float4 v[16];                         // 8 rows x 2 segments in flight
        {
            #pragma unroll
            for (int r = 0; r < 8; r++) {
                const int idx = ids[rbase + 8 * r];           // chunk 0 (user)
                const float4* src = (const float4*)(user_emb + (size_t)idx * 64);
                v[2 * r]     = __ldg(src + s8);
                v[2 * r + 1] = __ldg(src + s8 + 8);
            }
        }

        int s = 0;
        uint32_t par = 1;                     // fresh-barrier wait passes with parity 1
        for (int f = 0; f < NCHUNK; f++) {
            mbar_wait(mb_empty + s * 8, par);
            const uint32_t fullb = mb_full + s * 8;
            if (plane == 0) {
                mbar_expect_tx(fullb, W_TILE_BYTES);
                bulk_g2s(w0 + s * W_TILE_BYTES, g_Wtb + ((size_t)f << 13),
                         W_TILE_BYTES, fullb);
            }
            const uint32_t aS = a0 + s * A_TILE_BYTES;
            #pragma unroll
            for (int r = 0; r < 8; r++) {
                const uint32_t rowb = aS + (uint32_t)(rbase + 8 * r) * ROWB;
                sts64(rowb + off0, cvt2(v[2 * r].x,     v[2 * r].y),
                                   cvt2(v[2 * r].z,     v[2 * r].w));
                sts64(rowb + off1, cvt2(v[2 * r + 1].x, v[2 * r + 1].y),
                                   cvt2(v[2 * r + 1].z, v[2 * r + 1].w));
            }
            mbar_arrive(fullb);               // release: my STS are visible

            // prefetch next chunk's segments (latency overlaps waits/compute)
            if (f + 1 < NCHUNK) {
                const int fn = f + 1;
                const float* tbl = (fn == 1) ? item_emb
                                 : sparse_tables + (size_t)(fn - 2) * SPARSE_VOCAB * 64;
                #pragma unroll
                for (int r = 0; r < 8; r++) {
                    const int idx = ids[fn * TILE_B + rbase + 8 * r];
                    const float4* src = (const float4*)(tbl + (size_t)idx * 64);
                    v[2 * r]     = __ldg(src + s8);
                    v[2 * r + 1] = __ldg(src + s8 + 8);
                }
            }
            if (++s == STAGES) { s = 0; par ^= 1; }
        }
    } else {
        // ======== 8 consumer warps: 32x32 tiles, bf16 m16n8k16 ========
        const int wm = (wid & 1) * 32;        // M offset (batch rows, 0/32)
        const int wn = (wid >> 1) * 32;       // N offset (hidden cols, 0..96)
        const int g   = lane >> 2;
        const int tig = lane & 3;

        const uint32_t aRow = wm + (lane & 15);
        const uint32_t aHi  = lane >> 4;          // which 8-bf16 half of k16
        const uint32_t axor = aRow & 7;
        const uint32_t bRow = wn + (lane & 7) + ((lane >> 4) << 3);
        const uint32_t bHi  = (lane >> 3) & 1;
        const uint32_t bxor = bRow & 7;

        float acc[2][4][4];
        #pragma unroll
        for (int mt = 0; mt < 2; mt++)
            #pragma unroll
            for (int nt = 0; nt < 4; nt++)
                #pragma unroll
                for (int i = 0; i < 4; i++) acc[mt][nt][i] = 0.0f;

        int s = 0;
        uint32_t par = 0;
        for (int f = 0; f < NCHUNK; f++) {
            mbar_wait(mb_full + s * 8, par);
            const uint32_t aRowAddr = a0 + s * A_TILE_BYTES + aRow * ROWB;
            const uint32_t bRowAddr = w0 + s * W_TILE_BYTES + bRow * ROWB;

            #pragma unroll
            for (int it = 0; it < 4; it++) {           // K = 64 = 4 x k16
                uint32_t aa[2][4];
                uint32_t bb[2][4];
                const uint32_t blkA = ((it * 2 + aHi) ^ axor) << 4;
                const uint32_t blkB = ((it * 2 + bHi) ^ bxor) << 4;
                ldm4(aa[0], aRowAddr + blkA);
                ldm4(aa[1], aRowAddr + 16 * ROWB + blkA);
                ldm4(bb[0], bRowAddr + blkB);              // n-tiles 0,1
                ldm4(bb[1], bRowAddr + 16 * ROWB + blkB);  // n-tiles 2,3
                #pragma unroll
                for (int mt = 0; mt < 2; mt++)
                    #pragma unroll
                    for (int q2 = 0; q2 < 2; q2++) {
                        mma_bf16(acc[mt][q2 * 2 + 0], aa[mt], &bb[q2][0]);
                        mma_bf16(acc[mt][q2 * 2 + 1], aa[mt], &bb[q2][2]);
                    }
            }
            if (lane == 0) mbar_arrive(mb_empty + s * 8);
            if (++s == STAGES) { s = 0; par ^= 1; }
        }

        // epilogue: bias + relu + dot(W2) partials over this warp's 32 cols
        #pragma unroll
        for (int mt = 0; mt < 2; mt++) {
            float p0 = 0.0f, p1 = 0.0f;
            #pragma unroll
            for (int nt = 0; nt < 4; nt++) {
                const int col = wn + nt * 8 + 2 * tig;
                const float b1a = b1s[col], b1b = b1s[col + 1];
                const float w2a = w2s[col], w2b = w2s[col + 1];
                p0 += fmaxf(acc[mt][nt][0] + b1a, 0.0f) * w2a
                    + fmaxf(acc[mt][nt][1] + b1b, 0.0f) * w2b;
                p1 += fmaxf(acc[mt][nt][2] + b1a, 0.0f) * w2a
                    + fmaxf(acc[mt][nt][3] + b1b, 0.0f) * w2b;
            }
            p0 += __shfl_xor_sync(0xffffffffu, p0, 1);
            p0 += __shfl_xor_sync(0xffffffffu, p0, 2);
            p1 += __shfl_xor_sync(0xffffffffu, p1, 1);
            p1 += __shfl_xor_sync(0xffffffffu, p1, 2);
            if (tig == 0) {
                const int grp = wid >> 1;            // column quarter
                part[grp * TILE_B + wm + mt * 16 + g]     = p0;
                part[grp * TILE_B + wm + mt * 16 + g + 8] = p1;
            }
        }
    }
    __syncthreads();

    if (tid < TILE_B) {
        const float raw = part[tid] + part[TILE_B + tid] + part[2 * TILE_B + tid]
                        + part[3 * TILE_B + tid] + b2g[0];
        out[row0 + tid] = 1.0f / (1.0f + __expf(-raw));
    }
}

// ---------------- host ----------------
extern "C" void kernel_launch(void* const* d_in, const int* in_sizes, int n_in,
                              void* d_out, int out_size)
{
    const int*   user_ids        = (const int*)d_in[0];
    const int*   item_ids        = (const int*)d_in[1];
    const int*   sparse_features = (const int*)d_in[2];
    const float* user_emb        = (const float*)d_in[3];
    const float* item_emb        = (const float*)d_in[4];
    const float* sparse_tables   = (const float*)d_in[5];
    const float* W1              = (const float*)d_in[6];
    const float* b1              = (const float*)d_in[7];
    const float* W2              = (const float*)d_in[8];
    const float* b2              = (const float*)d_in[9];
    float*       out             = (float*)d_out;

    // pre-convert W1 into chunk-blocked, transposed, pre-swizzled bf16 scratch
    w1_prep_kernel<<<(1792 * 128 + 255) / 256, 256>>>(W1);

    cudaFuncSetAttribute(dlrm_fused7,
                         cudaFuncAttributeMaxDynamicSharedMemorySize, SMEM_DYN);
    dlrm_fused7<<<16384 / TILE_B, THREADS, SMEM_DYN>>>(
        user_ids, item_ids, sparse_features,
        user_emb, item_emb, sparse_tables,
        b1, W2, b2, out);
}